// round 6
// baseline (speedup 1.0000x reference)
#include <cuda_runtime.h>
#include <math.h>

#define NCOLS  16384
#define NT     512
#define V4     (NCOLS / 4 / NT)     // 8 float4 per thread (32 floats, in regs)
#define KSEL   256
#define CAP    4096
#define NW     (NT / 32)
#define GRID   304                  // ~2 CTAs/SM persistent

__global__ __launch_bounds__(NT, 2)
void entmax_topk_kernel(const float* __restrict__ logits,
                        float* __restrict__ out_w,
                        float* __restrict__ out_cnt,
                        int nrows)
{
    __shared__ float cand[CAP];
    __shared__ float s_f[NW];
    __shared__ int   s_i[NW];
    __shared__ float s_tau, s_th, s_inv;
    __shared__ int   s_useGe;

    const int tid  = threadIdx.x;
    const int lane = tid & 31;
    const int wid  = tid >> 5;
    const int stride = gridDim.x;

    int row = blockIdx.x;
    if (row >= nrows) return;

    // ---------- prologue: load first row (z = 0.5*logit), evict-first ----------
    float4 v[V4];
    {
        const float4* src = reinterpret_cast<const float4*>(logits) + (size_t)row * (NCOLS / 4);
        #pragma unroll
        for (int j = 0; j < V4; ++j) {
            float4 t = __ldcs(&src[tid + j * NT]);
            t.x *= 0.5f; t.y *= 0.5f; t.z *= 0.5f; t.w *= 0.5f;
            v[j] = t;
        }
    }

    while (true) {
        // ---------- block max ----------
        float lmax = -INFINITY;
        #pragma unroll
        for (int j = 0; j < V4; ++j)
            lmax = fmaxf(lmax, fmaxf(fmaxf(v[j].x, v[j].y), fmaxf(v[j].z, v[j].w)));
        #pragma unroll
        for (int o = 16; o; o >>= 1) lmax = fmaxf(lmax, __shfl_xor_sync(0xffffffffu, lmax, o));
        if (lane == 0) s_f[wid] = lmax;
        __syncthreads();                               // barrier A
        {
            float m = (lane < NW) ? s_f[lane] : -INFINITY;
            #pragma unroll
            for (int o = 8; o; o >>= 1) m = fmaxf(m, __shfl_xor_sync(0xffffffffu, m, o));
            lmax = __shfl_sync(0xffffffffu, m, 0);
        }
        const float zmax   = lmax;
        const float cutoff = zmax - 1.0f;              // rigorous lower bound on tau

        // ---------- compaction: candidates z > cutoff, from regs ----------
        int lc = 0;
        #pragma unroll
        for (int j = 0; j < V4; ++j) {
            lc += (v[j].x > cutoff) + (v[j].y > cutoff)
                + (v[j].z > cutoff) + (v[j].w > cutoff);
        }
        int inc = lc;
        #pragma unroll
        for (int o = 1; o < 32; o <<= 1) {
            int t = __shfl_up_sync(0xffffffffu, inc, o);
            if (lane >= o) inc += t;
        }
        if (lane == 31) s_i[wid] = inc;
        __syncthreads();                               // barrier B
        int wbase, cn;
        {
            int a = (lane < NW) ? s_i[lane] : 0;
            int sc = a;
            #pragma unroll
            for (int o = 1; o < NW; o <<= 1) {
                int u = __shfl_up_sync(0xffffffffu, sc, o);
                if (lane >= o) sc += u;
            }
            cn    = __shfl_sync(0xffffffffu, sc, NW - 1);
            wbase = __shfl_sync(0xffffffffu, sc - a, wid);
        }
        const bool useSmem = (cn <= CAP);
        if (useSmem && lc > 0) {
            int o = wbase + (inc - lc);
            #pragma unroll
            for (int j = 0; j < V4; ++j) {
                if (v[j].x > cutoff) cand[o++] = v[j].x;
                if (v[j].y > cutoff) cand[o++] = v[j].y;
                if (v[j].z > cutoff) cand[o++] = v[j].z;
                if (v[j].w > cutoff) cand[o++] = v[j].w;
            }
        }
        __syncthreads();                               // barrier C

        // ---------- tau solve: WARP 0 ONLY ----------
        if (wid == 0) {
            float tau = cutoff, th, inv;
            int useGe = 0;

            if (useSmem && cn <= 256) {
                float rv[8];
                #pragma unroll
                for (int r = 0; r < 8; ++r) {
                    int idx = r * 32 + lane;
                    rv[r] = (idx < cn) ? cand[idx] : -1e30f;
                }
                float gfin = 0.f;
                for (int it = 0; it < 24; ++it) {
                    float g = 0.f, gp = 0.f;
                    #pragma unroll
                    for (int r = 0; r < 8; ++r) {
                        float d = rv[r] - tau;
                        if (d > 0.f) { g = fmaf(d, d, g); gp += d; }
                    }
                    #pragma unroll
                    for (int o = 16; o; o >>= 1) {
                        g  += __shfl_xor_sync(0xffffffffu, g,  o);
                        gp += __shfl_xor_sync(0xffffffffu, gp, o);
                    }
                    gfin = g;
                    g -= 1.0f;
                    if (gp <= 0.f) break;
                    float step = g / (2.0f * gp);
                    tau += step;
                    if (step < 1e-7f) break;
                }
                int S = 0;
                #pragma unroll
                for (int r = 0; r < 8; ++r) S += (rv[r] > tau) ? 1 : 0;
                #pragma unroll
                for (int o = 16; o; o >>= 1) S += __shfl_xor_sync(0xffffffffu, S, o);

                th = tau;
                float ssum = gfin;
                if (S > KSEL) {                        // rare: bisect K-th largest z
                    useGe = 1;
                    float lo = tau, hi = zmax;
                    for (int it = 0; it < 48; ++it) {
                        float mid = 0.5f * (lo + hi);
                        int c = 0;
                        #pragma unroll
                        for (int r = 0; r < 8; ++r) c += (rv[r] >= mid) ? 1 : 0;
                        #pragma unroll
                        for (int o = 16; o; o >>= 1) c += __shfl_xor_sync(0xffffffffu, c, o);
                        if (c >= KSEL) lo = mid; else hi = mid;
                    }
                    th = lo;
                    ssum = 0.f;
                    #pragma unroll
                    for (int r = 0; r < 8; ++r) {
                        float z = rv[r], d = z - tau;
                        if (z >= th && d > 0.f) ssum = fmaf(d, d, ssum);
                    }
                    #pragma unroll
                    for (int o = 16; o; o >>= 1) ssum += __shfl_xor_sync(0xffffffffu, ssum, o);
                }
                inv = 1.0f / (ssum + 1e-8f);
            } else {
                const float* cb = useSmem ? cand : (logits + (size_t)row * NCOLS);
                const float  sc = useSmem ? 1.0f : 0.5f;
                const int    n  = useSmem ? cn : NCOLS;

                float gfin = 0.f;
                for (int it = 0; it < 24; ++it) {
                    float g = 0.f, gp = 0.f;
                    for (int i = lane; i < n; i += 32) {
                        float d = sc * cb[i] - tau;
                        if (d > 0.f) { g = fmaf(d, d, g); gp += d; }
                    }
                    #pragma unroll
                    for (int o = 16; o; o >>= 1) {
                        g  += __shfl_xor_sync(0xffffffffu, g,  o);
                        gp += __shfl_xor_sync(0xffffffffu, gp, o);
                    }
                    gfin = g;
                    g -= 1.0f;
                    if (gp <= 0.f) break;
                    float step = g / (2.0f * gp);
                    tau += step;
                    if (step < 1e-7f) break;
                }
                int S = 0;
                for (int i = lane; i < n; i += 32) S += (sc * cb[i] > tau) ? 1 : 0;
                #pragma unroll
                for (int o = 16; o; o >>= 1) S += __shfl_xor_sync(0xffffffffu, S, o);

                th = tau;
                float ssum = gfin;
                if (S > KSEL) {
                    useGe = 1;
                    float lo = tau, hi = zmax;
                    for (int it = 0; it < 48; ++it) {
                        float mid = 0.5f * (lo + hi);
                        int c = 0;
                        for (int i = lane; i < n; i += 32) c += (sc * cb[i] >= mid) ? 1 : 0;
                        #pragma unroll
                        for (int o = 16; o; o >>= 1) c += __shfl_xor_sync(0xffffffffu, c, o);
                        if (c >= KSEL) lo = mid; else hi = mid;
                    }
                    th = lo;
                    ssum = 0.f;
                    for (int i = lane; i < n; i += 32) {
                        float z = sc * cb[i], d = z - tau;
                        if (z >= th && d > 0.f) ssum = fmaf(d, d, ssum);
                    }
                    #pragma unroll
                    for (int o = 16; o; o >>= 1) ssum += __shfl_xor_sync(0xffffffffu, ssum, o);
                }
                inv = 1.0f / (ssum + 1e-8f);
            }
            if (lane == 0) { s_tau = tau; s_th = th; s_useGe = useGe; s_inv = inv; }
        }
        __syncthreads();                               // barrier D

        const float tau = s_tau, th = s_th, inv = s_inv;
        const int   useGe = s_useGe;

        // ---------- output + pipelined prefetch of next row ----------
        const int nextRow = row + stride;
        const bool hasNext = nextRow < nrows;
        float4* dst = reinterpret_cast<float4*>(out_w) + (size_t)row * (NCOLS / 4);
        int sel = 0;

        if (hasNext) {
            const float4* nsrc = reinterpret_cast<const float4*>(logits)
                               + (size_t)nextRow * (NCOLS / 4);
            #pragma unroll
            for (int j = 0; j < V4; ++j) {
                float4 w;
                {
                    float z = v[j].x, d = z - tau;
                    bool keep = useGe ? (z >= th && d > 0.f) : (d > 0.f);
                    w.x = keep ? d * d * inv : 0.f; sel += (w.x > 1e-6f);
                }
                {
                    float z = v[j].y, d = z - tau;
                    bool keep = useGe ? (z >= th && d > 0.f) : (d > 0.f);
                    w.y = keep ? d * d * inv : 0.f; sel += (w.y > 1e-6f);
                }
                {
                    float z = v[j].z, d = z - tau;
                    bool keep = useGe ? (z >= th && d > 0.f) : (d > 0.f);
                    w.z = keep ? d * d * inv : 0.f; sel += (w.z > 1e-6f);
                }
                {
                    float z = v[j].w, d = z - tau;
                    bool keep = useGe ? (z >= th && d > 0.f) : (d > 0.f);
                    w.w = keep ? d * d * inv : 0.f; sel += (w.w > 1e-6f);
                }
                float4 t = __ldcs(&nsrc[tid + j * NT]);   // next row, in flight early
                t.x *= 0.5f; t.y *= 0.5f; t.z *= 0.5f; t.w *= 0.5f;
                __stcs(&dst[tid + j * NT], w);
                v[j] = t;
            }
        } else {
            #pragma unroll
            for (int j = 0; j < V4; ++j) {
                float4 w;
                {
                    float z = v[j].x, d = z - tau;
                    bool keep = useGe ? (z >= th && d > 0.f) : (d > 0.f);
                    w.x = keep ? d * d * inv : 0.f; sel += (w.x > 1e-6f);
                }
                {
                    float z = v[j].y, d = z - tau;
                    bool keep = useGe ? (z >= th && d > 0.f) : (d > 0.f);
                    w.y = keep ? d * d * inv : 0.f; sel += (w.y > 1e-6f);
                }
                {
                    float z = v[j].z, d = z - tau;
                    bool keep = useGe ? (z >= th && d > 0.f) : (d > 0.f);
                    w.z = keep ? d * d * inv : 0.f; sel += (w.z > 1e-6f);
                }
                {
                    float z = v[j].w, d = z - tau;
                    bool keep = useGe ? (z >= th && d > 0.f) : (d > 0.f);
                    w.w = keep ? d * d * inv : 0.f; sel += (w.w > 1e-6f);
                }
                __stcs(&dst[tid + j * NT], w);
            }
        }

        #pragma unroll
        for (int o = 16; o; o >>= 1) sel += __shfl_xor_sync(0xffffffffu, sel, o);
        if (lane == 0) s_i[wid] = sel;
        __syncthreads();                               // barrier E
        if (tid == 0) {
            int t = 0;
            #pragma unroll
            for (int w = 0; w < NW; ++w) t += s_i[w];
            out_cnt[row] = (float)t;
        }

        if (!hasNext) break;
        row = nextRow;
    }
}

extern "C" void kernel_launch(void* const* d_in, const int* in_sizes, int n_in,
                              void* d_out, int out_size)
{
    const float* logits = (const float*)d_in[0];
    float* out = (float*)d_out;
    const int B = in_sizes[0] / NCOLS;
    const int grid = (B < GRID) ? B : GRID;
    entmax_topk_kernel<<<grid, NT>>>(logits, out, out + (size_t)B * NCOLS, B);
}